// round 3
// baseline (speedup 1.0000x reference)
#include <cuda_runtime.h>

// Double-pendulum Hamiltonian dynamics, closed form (M1=M2=L1=L2=1, G=9.81).
// State tp = (th1, th2, p1, p2) -> (dq1, dq2, dp1, dp2).
//
// c = cos(th1-th2), s = sin(th1-th2), D = 2 - c^2
// dq1 = (p1 - c p2)/D ; dq2 = (2 p2 - c p1)/D
// N = p1^2 - 2 c p1 p2 + 2 p2^2 ; dK/dc = (c N - D p1 p2)/D^2
// dp1 =  s dK/dc - 2 G sin(th1) ; dp2 = -s dK/dc - G sin(th2)
//
// R3: 256-bit loads/stores (sm_100+ ld/st.global.v8.f32) — one LDG.256 and
// one STG.256 per thread (2 states), halving memory-instruction count vs R2.

#define GCONST 9.81f

__device__ __forceinline__ float4 dyn(float th1, float th2, float p1, float p2) {
    float s, c;
    __sincosf(th1 - th2, &s, &c);

    float D    = 2.0f - c * c;
    float invD = __frcp_rn(D);

    float dq1 = (p1 - c * p2) * invD;
    float dq2 = (2.0f * p2 - c * p1) * invD;

    float p1p2 = p1 * p2;
    float N    = p1 * p1 - 2.0f * c * p1p2 + 2.0f * p2 * p2;
    float dKdc = (c * N - D * p1p2) * invD * invD;

    float sd = s * dKdc;
    float dp1 =  sd - 2.0f * GCONST * __sinf(th1);
    float dp2 = -sd -        GCONST * __sinf(th2);

    return make_float4(dq1, dq2, dp1, dp2);
}

__global__ void __launch_bounds__(256)
pendelum2dof_kernel(const float* __restrict__ y,
                    float* __restrict__ out,
                    int npairs) {
    int i = blockIdx.x * blockDim.x + threadIdx.x;   // one thread = 2 states = 32 B
    if (i >= npairs) return;

    const float* src = y + (size_t)i * 8;
    float a0, a1, a2, a3, a4, a5, a6, a7;
    asm volatile("ld.global.v8.f32 {%0,%1,%2,%3,%4,%5,%6,%7}, [%8];"
                 : "=f"(a0), "=f"(a1), "=f"(a2), "=f"(a3),
                   "=f"(a4), "=f"(a5), "=f"(a6), "=f"(a7)
                 : "l"(src));

    float4 r0 = dyn(a0, a1, a2, a3);
    float4 r1 = dyn(a4, a5, a6, a7);

    float* dst = out + (size_t)i * 8;
    asm volatile("st.global.v8.f32 [%0], {%1,%2,%3,%4,%5,%6,%7,%8};"
                 :
                 : "l"(dst),
                   "f"(r0.x), "f"(r0.y), "f"(r0.z), "f"(r0.w),
                   "f"(r1.x), "f"(r1.y), "f"(r1.z), "f"(r1.w)
                 : "memory");
}

extern "C" void kernel_launch(void* const* d_in, const int* in_sizes, int n_in,
                              void* d_out, int out_size) {
    // d_in[0] = t (unused), d_in[1] = y (B*4 floats), B = 262144 (even)
    const float* y = (const float*)d_in[1];
    float* out = (float*)d_out;
    int nstates = in_sizes[1] / 4;
    int npairs  = nstates / 2;        // B even; each thread does 2 states

    const int TPB = 256;
    int blocks = (npairs + TPB - 1) / TPB;
    pendelum2dof_kernel<<<blocks, TPB>>>(y, out, npairs);
}